// round 16
// baseline (speedup 1.0000x reference)
#include <cuda_runtime.h>
#include <cuda_fp16.h>
#include <math.h>
#include <stdint.h>

#define DIMV   1024
#define HEADS  16
#define DHV    64
#define NV     1024
#define BV     2
#define JV     5120
#define MEMR   4096

// Scratch (__device__ globals per allocation rules)
__device__ __half g_KXh[BV * JV * DIMV];           // fp16 concat(mem, x)
__device__ __half g_WhT[4 * DIMV * DIMV];          // fp16 W^T [mode][n][k]; Wq*0.125*log2e
__device__ __half g_Qh [BV * NV * DIMV];           // q, pre-scaled (log2 domain)
__device__ __half g_Kh [BV * JV * DIMV];           // k + rel bias
__device__ __half g_VhT[BV * HEADS * DHV * JV];    // v transposed [b][h][d][j]
__device__ __half g_Oh [BV * NV * DIMV];           // attn out (fp16)

__device__ __forceinline__ uint32_t pack2(float lo, float hi) {
    __half2 h = __floats2half2_rn(lo, hi);
    return *(uint32_t*)&h;
}
__device__ __forceinline__ uint32_t sptr(const void* p) {
    return (uint32_t)__cvta_generic_to_shared(p);
}
__device__ __forceinline__ float ex2f(float x) {
    float r;
    asm("ex2.approx.f32 %0, %1;" : "=f"(r) : "f"(x));
    return r;
}
__device__ __forceinline__ uint32_t ex2h2(uint32_t x) {
    uint32_t r;
    asm("ex2.approx.f16x2 %0, %1;" : "=r"(r) : "r"(x));
    return r;
}

#define CP16(dst, src)                                                        \
    asm volatile("cp.async.cg.shared.global [%0], [%1], 16;"                  \
                 :: "r"(dst), "l"(src))
#define CP_COMMIT() asm volatile("cp.async.commit_group;")
#define CP_WAIT0()  asm volatile("cp.async.wait_group 0;")
#define CP_WAIT1()  asm volatile("cp.async.wait_group 1;")
#define CP_WAIT2()  asm volatile("cp.async.wait_group 2;")

#define LDSM_X4(r0, r1, r2, r3, addr)                                         \
    asm volatile("ldmatrix.sync.aligned.m8n8.x4.shared.b16 {%0,%1,%2,%3},[%4];" \
                 : "=r"(r0), "=r"(r1), "=r"(r2), "=r"(r3) : "r"(addr))

#define MMA_F16(c, a, b0_, b1_)                                               \
    asm volatile(                                                             \
        "mma.sync.aligned.m16n8k16.row.col.f32.f16.f16.f32 "                  \
        "{%0,%1,%2,%3},{%4,%5,%6,%7},{%8,%9},{%0,%1,%2,%3};"                  \
        : "+f"(c[0]), "+f"(c[1]), "+f"(c[2]), "+f"(c[3])                      \
        : "r"(a[0]), "r"(a[1]), "r"(a[2]), "r"(a[3]), "r"(b0_), "r"(b1_))

// ---------------------------------------------------------------------------
// Merged pre-pass:
//   [0,5120)      kx fp16 convert
//   [5120,9216)   weight fp16 convert + TRANSPOSE to [n][k] (4096 tiles 32x32)
//   [9216,11264)  new_mem copy
// ---------------------------------------------------------------------------
__global__ __launch_bounds__(256)
void conv_all(const float* __restrict__ x, const float* __restrict__ mem,
              const float* __restrict__ Wq, const float* __restrict__ Wk,
              const float* __restrict__ Wv, const float* __restrict__ Wo,
              float* __restrict__ out_tail)
{
    __shared__ float tsm[32][33];

    if (blockIdx.x < 5120) {
        int i = blockIdx.x * blockDim.x + threadIdx.x;
        int e = i * 8;
        int b = e / (JV * DIMV);
        int rem = e - b * (JV * DIMV);
        int r = rem >> 10, c = rem & 1023;
        const float* src = (r < MEMR) ? mem + ((size_t)(b * MEMR + r) << 10) + c
                                      : x   + ((size_t)(b * NV + r - MEMR) << 10) + c;
        float4 v0 = *(const float4*)(src);
        float4 v1 = *(const float4*)(src + 4);
        uint4 o;
        o.x = pack2(v0.x, v0.y); o.y = pack2(v0.z, v0.w);
        o.z = pack2(v1.x, v1.y); o.w = pack2(v1.z, v1.w);
        *(uint4*)(g_KXh + e) = o;
    } else if (blockIdx.x < 9216) {
        int t    = blockIdx.x - 5120;
        int mode = t >> 10;
        int rem  = t & 1023;
        int k0   = (rem & 31) * 32;
        int n0   = (rem >> 5) * 32;
        const float* W = (mode == 0) ? Wq : (mode == 1) ? Wk
                       : (mode == 2) ? Wv : Wo;
        float s = (mode == 0) ? 0.125f * 1.4426950408889634f : 1.0f;
        int tx = threadIdx.x & 31, ty = threadIdx.x >> 5;   // 32 x 8
#pragma unroll
        for (int i = 0; i < 4; i++)
            tsm[ty + 8 * i][tx] = W[(size_t)(k0 + ty + 8 * i) * DIMV + n0 + tx];
        __syncthreads();
        __half* dst = g_WhT + (size_t)mode * DIMV * DIMV;
#pragma unroll
        for (int i = 0; i < 4; i++)
            dst[(size_t)(n0 + ty + 8 * i) * DIMV + k0 + tx] =
                __float2half(tsm[tx][ty + 8 * i] * s);
    } else {
        // new_mem = x (seq_len == N)
        int i = (blockIdx.x - 9216) * blockDim.x + threadIdx.x;
        ((float4*)out_tail)[i] = ((const float4*)x)[i];
    }
}

// ---------------------------------------------------------------------------
// fp16 GEMM, BK=64, 3-stage cp.async, non-trans ldmatrix both operands
// (W pre-transposed to [n][k]). 8 warps (2x4), 256 threads.
// PHASE 0: fused QKV projections, M-tile 128; PHASE 1: out projection, M 64.
// ---------------------------------------------------------------------------
#define WSTG_T 18432            // 128 n-rows * 144B

template <int PHASE>
__global__ __launch_bounds__(256, 2)
void gemm_h(const int* __restrict__ rel_idxs,
            const float* __restrict__ rel_table,
            const float* __restrict__ bo, float* __restrict__ Cout)
{
    constexpr int MR   = (PHASE == 0) ? 128 : 64;
    constexpr int MI   = MR / 32;
    constexpr int ASTG = MR * 144;

    extern __shared__ char gsm[];
    const uint32_t GA = sptr(gsm);
    const uint32_t GW = GA + 3 * ASTG;

    int mode, mb;
    if (PHASE == 0) {
        const int bx = blockIdx.x;
        if (bx < 16)      { mode = 0; mb = bx; }
        else if (bx < 96) { mode = 1; mb = bx - 16; }
        else              { mode = 2; mb = bx - 96; }
    } else { mode = 3; mb = blockIdx.x; }

    const int bmRow = mb * MR;
    int bmA = bmRow;
    if (PHASE == 0 && mode == 0)
        bmA = (mb >> 3) * JV + MEMR + (mb & 7) * 128;

    const __half* Abase = (PHASE == 0) ? g_KXh : g_Oh;
    const __half* WbT   = g_WhT + (size_t)mode * DIMV * DIMV;
    const int bn   = blockIdx.y * 128;
    const int tid  = threadIdx.x;
    const int warp = tid >> 5;
    const int lane = tid & 31;
    const int wm   = warp >> 2;
    const int wn   = warp & 3;
    const int g    = lane >> 2;
    const int tg   = lane & 3;

    // cp.async: A (MR rows x 64 halves) and W^T (128 rows x 64 halves)
    const int arow = tid >> 3, aseg = tid & 7;
    const int wrow = tid >> 1, wseg = tid & 1;      // half-row (64B) per thread
    const __half* aS = Abase + (size_t)(bmA + arow) * DIMV + aseg * 8;
    const __half* wS = WbT   + (size_t)(bn + wrow) * DIMV + wseg * 32;
    const uint32_t aD = GA + arow * 144 + aseg * 16;
    const uint32_t wD = GW + wrow * 144 + wseg * 64;

    // ldmatrix lane addresses (both non-trans, K-tile pattern)
    const uint32_t a_addr = GA + (wm * (MR / 2) + (lane & 15)) * 144 + (lane >> 4) * 16;
    const uint32_t w_addr = GW + (wn * 32 + ((lane >> 4) * 8 + (lane & 7))) * 144
                               + ((lane >> 3) & 1) * 16;

    float acc[MI][4][4];
#pragma unroll
    for (int mi = 0; mi < MI; mi++)
#pragma unroll
        for (int ni = 0; ni < 4; ni++)
#pragma unroll
            for (int r = 0; r < 4; r++) acc[mi][ni][r] = 0.f;

    auto issue = [&](int s) {
        const int k0 = s * 64;
        const int st = s % 3;
        const uint32_t so = (uint32_t)st * ASTG;
        const uint32_t sw = (uint32_t)st * WSTG_T;
#pragma unroll
        for (int i = 0; i < MI; i++)
            CP16(aD + so + i * (32 * 144), aS + (size_t)(32 * i) * DIMV + k0);
        // W^T slab: 128 rows x 128B; each thread copies 64B (4 chunks)
#pragma unroll
        for (int i = 0; i < 4; i++)
            CP16(wD + sw + i * 16, wS + k0 + i * 8);
        CP_COMMIT();
    };

    issue(0); issue(1);

    for (int s = 0; s < 16; s++) {
        if (s + 1 < 16) { CP_WAIT1(); } else { CP_WAIT0(); }
        __syncthreads();           // stage s ready; all warps past stage s-1
        if (s + 2 < 16) issue(s + 2);

        const int st = s % 3;
        const uint32_t soA = (uint32_t)st * ASTG;
        const uint32_t soW = (uint32_t)st * WSTG_T;
#pragma unroll
        for (int kb = 0; kb < 4; kb++) {
            uint32_t a[MI][4];
#pragma unroll
            for (int mi = 0; mi < MI; mi++)
                LDSM_X4(a[mi][0], a[mi][1], a[mi][2], a[mi][3],
                        a_addr + soA + mi * 2304 + kb * 32);
            uint32_t b[4][2];
#pragma unroll
            for (int nb = 0; nb < 2; nb++)
                LDSM_X4(b[2 * nb][0], b[2 * nb][1], b[2 * nb + 1][0], b[2 * nb + 1][1],
                        w_addr + soW + nb * (16 * 144) + kb * 32);
#pragma unroll
            for (int mi = 0; mi < MI; mi++)
#pragma unroll
                for (int ni = 0; ni < 4; ni++)
                    MMA_F16(acc[mi][ni], a[mi], b[ni][0], b[ni][1]);
        }
    }

    // Epilogue
#pragma unroll
    for (int mi = 0; mi < MI; mi++) {
#pragma unroll
        for (int r2 = 0; r2 < 2; r2++) {
            int row = bmRow + wm * (MR / 2) + mi * 16 + g + 8 * r2;
            int mslot = 0;
            if (PHASE == 0 && mode == 1) {
                int jj = row % JV;
                mslot = (jj < MEMR) ? (jj >> 10) : 4;
            }
#pragma unroll
            for (int ni = 0; ni < 4; ni++) {
                int col = bn + wn * 32 + ni * 8 + 2 * tg;
                float c0 = acc[mi][ni][r2 * 2];
                float c1 = acc[mi][ni][r2 * 2 + 1];
                if (PHASE == 1) {
                    Cout[(size_t)row * DIMV + col]     = c0 + bo[col];
                    Cout[(size_t)row * DIMV + col + 1] = c1 + bo[col + 1];
                } else if (mode == 0) {
                    *(__half2*)(g_Qh + (size_t)row * DIMV + col) =
                        __floats2half2_rn(c0, c1);
                } else if (mode == 1) {
                    float bias = rel_table[rel_idxs[mslot] * HEADS + (col >> 6)];
                    *(__half2*)(g_Kh + (size_t)row * DIMV + col) =
                        __floats2half2_rn(c0 + bias, c1 + bias);
                } else {
                    int jj = row % JV, bb = row / JV;
                    int hh = col >> 6, d = col & 63;
                    __half* p = g_VhT + ((size_t)(bb * HEADS + hh) * DHV + d) * JV + jj;
                    p[0]  = __float2half(c0);
                    p[JV] = __float2half(c1);
                }
            }
        }
    }
}

#define GEMM_SMEM0 (3 * (128 * 144 + WSTG_T))   // 110592
#define GEMM_SMEM1 (3 * (64 * 144 + WSTG_T))    // 82944

// ---------------------------------------------------------------------------
// Flash attention (unchanged from R14 winner): fp16 mma.sync, ldmatrix,
// Q frags hoisted, P in registers, K/V 4-stage cp.async, SIMD fp16x2 exp2
// softmax, row-sum via ones-MMA. 8 warps, warp tile 16x64.
// ---------------------------------------------------------------------------
#define QST 36
#define KST 36
#define VTS 36
#define KV_STG (64 * 144)
#define NSTG 4

__global__ __launch_bounds__(256, 2)
void attn_h()
{
    extern __shared__ uint32_t asmem[];
    uint32_t* Qs  = asmem;                     // [128][36]
    uint32_t* Ks  = Qs + 128 * QST;            // [4][64][36]
    uint32_t* VsT = Ks + NSTG * 64 * KST;      // [4][64][36]

    const int qt  = blockIdx.x;
    const int bh  = blockIdx.y;
    const int b   = bh >> 4;
    const int h   = bh & 15;
    const int tid = threadIdx.x;
    const int warp = tid >> 5;
    const int lane = tid & 31;
    const int g    = lane >> 2;
    const int tg   = lane & 3;
    const int q0   = qt * 128;
    const int rb   = warp * 16;
    const uint32_t ONE2 = 0x3C003C00u;         // packed fp16 {1, 1}

    // Load Q tile into smem
    {
        int qrow = tid >> 1, qc = (tid & 1) * 32;
        const __half* src = g_Qh + ((size_t)(b * NV + q0 + qrow)) * DIMV + h * DHV + qc;
#pragma unroll
        for (int p = 0; p < 4; p++)
            *(uint4*)&Qs[qrow * QST + (qc >> 1) + 4 * p] = ((const uint4*)src)[p];
    }

    float o[8][4];
    float m_i[2], l_i[2];
#pragma unroll
    for (int rh = 0; rh < 2; rh++) { m_i[rh] = -INFINITY; l_i[rh] = 0.f; }
#pragma unroll
    for (int ni = 0; ni < 8; ni++)
#pragma unroll
        for (int r = 0; r < 4; r++) o[ni][r] = 0.f;

    const int ktiles = 2 * qt + 66;

    const int kj  = tid >> 2;
    const int kch = (tid & 3) * 16;
    const __half* kbase = g_Kh + ((size_t)(b * JV + kj)) * DIMV + h * DHV + kch;
    const int vd = tid >> 2;
    const int vq = (tid & 3) * 8;
    const __half* vbase = g_VhT + (((size_t)(b * HEADS + h) * DHV + vd) * JV) + vq * 2;

    const uint32_t ksd = sptr(Ks)  + kj * 144 + (tid & 3) * 32;
    const uint32_t vsd = sptr(VsT) + vd * 144 + (tid & 3) * 32;

    const uint32_t q_addr =
        sptr(Qs) + (uint32_t)((rb + (lane & 15)) * 144 + (lane >> 4) * 16);
    const uint32_t kv_lane =
        (uint32_t)((((lane >> 4) * 8 + (lane & 7)) * 36 + 4 * ((lane >> 3) & 1)) * 4);
    const uint32_t ks_base = sptr(Ks) + kv_lane;
    const uint32_t vs_base = sptr(VsT) + kv_lane;

    auto issue_kv = [&](int tile) {
        const uint32_t so = (uint32_t)(tile % NSTG) * KV_STG;
        const __half* kp_ = kbase + (size_t)tile * 64 * DIMV;
        const __half* vp_ = vbase + (size_t)tile * 64;
        CP16(ksd + so, kp_); CP16(ksd + so + 16, kp_ + 8);
        CP16(vsd + so, vp_); CP16(vsd + so + 16, vp_ + 8);
        CP_COMMIT();
    };

    issue_kv(0); issue_kv(1); issue_kv(2);
    __syncthreads();   // Q smem visible

    uint32_t aq[4][4];
#pragma unroll
    for (int kb = 0; kb < 4; kb++)
        LDSM_X4(aq[kb][0], aq[kb][1], aq[kb][2], aq[kb][3], q_addr + kb * 32);

    for (int kt = 0; kt < ktiles; kt++) {
        if (kt + 2 < ktiles)      { CP_WAIT2(); }
        else if (kt + 1 < ktiles) { CP_WAIT1(); }
        else                      { CP_WAIT0(); }
        __syncthreads();

        if (kt + 3 < ktiles) issue_kv(kt + 3);

        const uint32_t so = (uint32_t)(kt % NSTG) * KV_STG;
        const uint32_t kst = ks_base + so;
        const uint32_t vst = vs_base + so;

        // S = Q K^T (log2 domain)
        float s[8][4];
#pragma unroll
        for (int ni = 0; ni < 8; ni++)
#pragma unroll
            for (int r = 0; r < 4; r++) s[ni][r] = 0.f;
#pragma unroll
        for (int kb = 0; kb < 4; kb++) {
#pragma unroll
            for (int nq = 0; nq < 4; nq++) {
                uint32_t b0, b1, b2, b3;
                LDSM_X4(b0, b1, b2, b3, kst + nq * (16 * 144) + kb * 32);
                MMA_F16(s[2 * nq],     aq[kb], b0, b1);
                MMA_F16(s[2 * nq + 1], aq[kb], b2, b3);
            }
        }

        // Causal mask on boundary tiles
        const int j0 = kt * 64;
        if (kt >= 2 * qt + 64) {
#pragma unroll
            for (int rh = 0; rh < 2; rh++) {
                int ii = q0 + rb + g + 8 * rh;
#pragma unroll
                for (int ni = 0; ni < 8; ni++)
#pragma unroll
                    for (int c2 = 0; c2 < 2; c2++) {
                        int jc = j0 + ni * 8 + 2 * tg + c2;
                        if (jc > ii + 4096) s[ni][rh * 2 + c2] = -1e30f;
                    }
            }
        }

        // Online softmax (exp2 domain): max-reduce + SIMD ex2; row sum via
        // tensor core below (P x ones).
        uint32_t pa[8][2];
        float fac[2];
#pragma unroll
        for (int rh = 0; rh < 2; rh++) {
            float mx = -INFINITY;
#pragma unroll
            for (int ni = 0; ni < 8; ni++)
                mx = fmaxf(mx, fmaxf(s[ni][2 * rh], s[ni][2 * rh + 1]));
            mx = fmaxf(mx, __shfl_xor_sync(0xffffffffu, mx, 1));
            mx = fmaxf(mx, __shfl_xor_sync(0xffffffffu, mx, 2));
            float mnew = fmaxf(m_i[rh], mx);
            fac[rh] = ex2f(m_i[rh] - mnew);
            m_i[rh] = mnew;
#pragma unroll
            for (int ni = 0; ni < 8; ni++)
                pa[ni][rh] = ex2h2(pack2(s[ni][2 * rh] - mnew,
                                         s[ni][2 * rh + 1] - mnew));
#pragma unroll
            for (int ni = 0; ni < 8; ni++) {
                o[ni][2 * rh]     *= fac[rh];
                o[ni][2 * rh + 1] *= fac[rh];
            }
        }

        // O += P V, and lsum = P x ones (row sums on the tensor pipe)
        float lsum[4] = { 0.f, 0.f, 0.f, 0.f };
#pragma unroll
        for (int kb = 0; kb < 4; kb++) {
            uint32_t a[4] = { pa[2 * kb][0], pa[2 * kb][1],
                              pa[2 * kb + 1][0], pa[2 * kb + 1][1] };
            MMA_F16(lsum, a, ONE2, ONE2);
#pragma unroll
            for (int nq = 0; nq < 4; nq++) {
                uint32_t b0, b1, b2, b3;
                LDSM_X4(b0, b1, b2, b3, vst + nq * (16 * 144) + kb * 32);
                MMA_F16(o[2 * nq],     a, b0, b1);
                MMA_F16(o[2 * nq + 1], a, b2, b3);
            }
        }
        l_i[0] = l_i[0] * fac[0] + lsum[0];
        l_i[1] = l_i[1] * fac[1] + lsum[2];
    }

    // Normalize, write O (fp16)
#pragma unroll
    for (int rh = 0; rh < 2; rh++) {
        float inv = 1.f / l_i[rh];
        int row = q0 + rb + g + 8 * rh;
        __half* dst = g_Oh + (size_t)(b * NV + row) * DIMV + h * DHV;
#pragma unroll
        for (int ni = 0; ni < 8; ni++) {
            *(__half2*)(dst + ni * 8 + 2 * tg) =
                __floats2half2_rn(o[ni][2 * rh] * inv, o[ni][2 * rh + 1] * inv);
        }
    }
}

static const size_t ATTN_SMEM =
    (size_t)(128 * QST + NSTG * 64 * KST + NSTG * 64 * VTS) * sizeof(uint32_t); // 92160

extern "C" void kernel_launch(void* const* d_in, const int* in_sizes, int n_in,
                              void* d_out, int out_size)
{
    const float* x    = (const float*)d_in[0];
    const float* mem  = (const float*)d_in[1];
    const int*   ridx = (const int*)d_in[3];
    const float* Wq   = (const float*)d_in[4];
    const float* Wk   = (const float*)d_in[5];
    const float* Wv   = (const float*)d_in[6];
    const float* Wo   = (const float*)d_in[7];
    const float* bo   = (const float*)d_in[8];
    const float* rtab = (const float*)d_in[9];
    float* out = (float*)d_out;

    cudaFuncSetAttribute(attn_h, cudaFuncAttributeMaxDynamicSharedMemorySize,
                         (int)ATTN_SMEM);
    cudaFuncSetAttribute(gemm_h<0>, cudaFuncAttributeMaxDynamicSharedMemorySize,
                         GEMM_SMEM0);
    cudaFuncSetAttribute(gemm_h<1>, cudaFuncAttributeMaxDynamicSharedMemorySize,
                         GEMM_SMEM1);

    conv_all<<<11264, 256>>>(x, mem, Wq, Wk, Wv, Wo,
                             out + (size_t)BV * NV * DIMV);
    gemm_h<0><<<dim3(176, 8), 256, GEMM_SMEM0>>>(ridx, rtab, bo, nullptr);
    attn_h<<<dim3(8, 32), 256, ATTN_SMEM>>>();
    gemm_h<1><<<dim3(32, 8), 256, GEMM_SMEM1>>>(ridx, rtab, bo, out);
}

// round 17
// speedup vs baseline: 1.1105x; 1.1105x over previous
#include <cuda_runtime.h>
#include <cuda_fp16.h>
#include <math.h>
#include <stdint.h>

#define DIMV   1024
#define HEADS  16
#define DHV    64
#define NV     1024
#define BV     2
#define JV     5120
#define MEMR   4096

// Scratch (__device__ globals per allocation rules)
__device__ __half g_KXh[BV * JV * DIMV];           // fp16 concat(mem, x)
__device__ __half g_Wh [4 * DIMV * DIMV];          // fp16 Wq(*0.125*log2e), Wk, Wv, Wo
__device__ __half g_Qh [BV * NV * DIMV];           // q, pre-scaled (log2 domain)
__device__ __half g_Kh [BV * JV * DIMV];           // k + rel bias
__device__ __half g_VhT[BV * HEADS * DHV * JV];    // v transposed [b][h][d][j]
__device__ __half g_Oh [BV * NV * DIMV];           // attn out (fp16)

__device__ __forceinline__ uint32_t pack2(float lo, float hi) {
    __half2 h = __floats2half2_rn(lo, hi);
    return *(uint32_t*)&h;
}
__device__ __forceinline__ uint32_t sptr(const void* p) {
    return (uint32_t)__cvta_generic_to_shared(p);
}
__device__ __forceinline__ float ex2f(float x) {
    float r;
    asm("ex2.approx.f32 %0, %1;" : "=f"(r) : "f"(x));
    return r;
}
__device__ __forceinline__ uint32_t ex2h2(uint32_t x) {
    uint32_t r;
    asm("ex2.approx.f16x2 %0, %1;" : "=r"(r) : "r"(x));
    return r;
}

#define CP16(dst, src)                                                        \
    asm volatile("cp.async.cg.shared.global [%0], [%1], 16;"                  \
                 :: "r"(dst), "l"(src))
#define CP_COMMIT() asm volatile("cp.async.commit_group;")
#define CP_WAIT0()  asm volatile("cp.async.wait_group 0;")
#define CP_WAIT1()  asm volatile("cp.async.wait_group 1;")
#define CP_WAIT2()  asm volatile("cp.async.wait_group 2;")

#define LDSM_X4(r0, r1, r2, r3, addr)                                         \
    asm volatile("ldmatrix.sync.aligned.m8n8.x4.shared.b16 {%0,%1,%2,%3},[%4];" \
                 : "=r"(r0), "=r"(r1), "=r"(r2), "=r"(r3) : "r"(addr))

#define LDSM_X4_T(r0, r1, r2, r3, addr)                                       \
    asm volatile("ldmatrix.sync.aligned.m8n8.x4.trans.shared.b16 {%0,%1,%2,%3},[%4];" \
                 : "=r"(r0), "=r"(r1), "=r"(r2), "=r"(r3) : "r"(addr))

#define MMA_F16(c, a, b0_, b1_)                                               \
    asm volatile(                                                             \
        "mma.sync.aligned.m16n8k16.row.col.f32.f16.f16.f32 "                  \
        "{%0,%1,%2,%3},{%4,%5,%6,%7},{%8,%9},{%0,%1,%2,%3};"                  \
        : "+f"(c[0]), "+f"(c[1]), "+f"(c[2]), "+f"(c[3])                      \
        : "r"(a[0]), "r"(a[1]), "r"(a[2]), "r"(a[3]), "r"(b0_), "r"(b1_))

// ---------------------------------------------------------------------------
// Merged pre-pass: kx fp16 convert | weight fp16 convert | new_mem copy
// ---------------------------------------------------------------------------
__global__ __launch_bounds__(256)
void conv_all(const float* __restrict__ x, const float* __restrict__ mem,
              const float* __restrict__ Wq, const float* __restrict__ Wk,
              const float* __restrict__ Wv, const float* __restrict__ Wo,
              float* __restrict__ out_tail)
{
    if (blockIdx.x < 5120) {
        int i = blockIdx.x * blockDim.x + threadIdx.x;
        int e = i * 8;
        int b = e / (JV * DIMV);
        int rem = e - b * (JV * DIMV);
        int r = rem >> 10, c = rem & 1023;
        const float* src = (r < MEMR) ? mem + ((size_t)(b * MEMR + r) << 10) + c
                                      : x   + ((size_t)(b * NV + r - MEMR) << 10) + c;
        float4 v0 = *(const float4*)(src);
        float4 v1 = *(const float4*)(src + 4);
        uint4 o;
        o.x = pack2(v0.x, v0.y); o.y = pack2(v0.z, v0.w);
        o.z = pack2(v1.x, v1.y); o.w = pack2(v1.z, v1.w);
        *(uint4*)(g_KXh + e) = o;
    } else if (blockIdx.x < 7168) {
        int i = (blockIdx.x - 5120) * blockDim.x + threadIdx.x;
        int e = i * 8;
        int w = e >> 20;
        int off = e & ((1 << 20) - 1);
        const float* src = (w == 0 ? Wq : w == 1 ? Wk : w == 2 ? Wv : Wo) + off;
        float s = (w == 0) ? 0.125f * 1.4426950408889634f : 1.0f;
        float4 v0 = *(const float4*)(src);
        float4 v1 = *(const float4*)(src + 4);
        uint4 o;
        o.x = pack2(v0.x * s, v0.y * s); o.y = pack2(v0.z * s, v0.w * s);
        o.z = pack2(v1.x * s, v1.y * s); o.w = pack2(v1.z * s, v1.w * s);
        *(uint4*)(g_Wh + e) = o;
    } else {
        // new_mem = x (seq_len == N)
        int i = (blockIdx.x - 7168) * blockDim.x + threadIdx.x;
        ((float4*)out_tail)[i] = ((const float4*)x)[i];
    }
}

// ---------------------------------------------------------------------------
// fp16 GEMM, BK=64, 3-stage cp.async, ldmatrix, 8 warps (2x4), 256 threads.
// blockIdx.x = n-tile (A-slab shared across consecutive CTAs for L2 locality)
// PHASE 0: fused QKV projections, M-tile 128; PHASE 1: out projection, M 64.
// ---------------------------------------------------------------------------
#define WSTG 17408              // 64 rows * 272B

template <int PHASE>
__global__ __launch_bounds__(256, 2)
void gemm_h(const int* __restrict__ rel_idxs,
            const float* __restrict__ rel_table,
            const float* __restrict__ bo, float* __restrict__ Cout)
{
    constexpr int MR   = (PHASE == 0) ? 128 : 64;
    constexpr int MI   = MR / 32;
    constexpr int ASTG = MR * 144;

    extern __shared__ char gsm[];
    const uint32_t GA = sptr(gsm);
    const uint32_t GW = GA + 3 * ASTG;

    int mode, mb;
    if (PHASE == 0) {
        const int by = blockIdx.y;
        if (by < 16)      { mode = 0; mb = by; }
        else if (by < 96) { mode = 1; mb = by - 16; }
        else              { mode = 2; mb = by - 96; }
    } else { mode = 3; mb = blockIdx.y; }

    const int bmRow = mb * MR;
    int bmA = bmRow;
    if (PHASE == 0 && mode == 0)
        bmA = (mb >> 3) * JV + MEMR + (mb & 7) * 128;

    const __half* Abase = (PHASE == 0) ? g_KXh : g_Oh;
    const __half* Wbase = g_Wh + (size_t)mode * DIMV * DIMV;
    const int bn   = blockIdx.x * 128;
    const int tid  = threadIdx.x;
    const int warp = tid >> 5;
    const int lane = tid & 31;
    const int wm   = warp >> 2;
    const int wn   = warp & 3;
    const int g    = lane >> 2;
    const int tg   = lane & 3;

    const int arow = tid >> 3, aseg = tid & 7;
    const int wrow = tid >> 4, wseg = tid & 15;
    const __half* aS = Abase + (size_t)(bmA + arow) * DIMV + aseg * 8;
    const __half* wS = Wbase + (size_t)wrow * DIMV + bn + wseg * 8;
    const uint32_t aD = GA + arow * 144 + aseg * 16;
    const uint32_t wD = GW + wrow * 272 + wseg * 16;

    const uint32_t a_addr = GA + (wm * (MR / 2) + (lane & 15)) * 144 + (lane >> 4) * 16;
    const uint32_t w_addr = GW + (8 * ((lane >> 3) & 1) + (lane & 7)) * 272
                               + (wn * 32 + (lane >> 4) * 8) * 2;

    float acc[MI][4][4];
#pragma unroll
    for (int mi = 0; mi < MI; mi++)
#pragma unroll
        for (int ni = 0; ni < 4; ni++)
#pragma unroll
            for (int r = 0; r < 4; r++) acc[mi][ni][r] = 0.f;

    auto issue = [&](int s) {
        const int k0 = s * 64;
        const int st = s % 3;
        const uint32_t so = (uint32_t)st * ASTG;
        const uint32_t sw = (uint32_t)st * WSTG;
#pragma unroll
        for (int i = 0; i < MI; i++)
            CP16(aD + so + i * (32 * 144), aS + (size_t)(32 * i) * DIMV + k0);
#pragma unroll
        for (int i = 0; i < 4; i++)
            CP16(wD + sw + i * (16 * 272), wS + (size_t)(k0 + 16 * i) * DIMV);
        CP_COMMIT();
    };

    issue(0); issue(1);

    for (int s = 0; s < 16; s++) {
        if (s + 1 < 16) { CP_WAIT1(); } else { CP_WAIT0(); }
        __syncthreads();           // stage s ready; all warps past stage s-1
        if (s + 2 < 16) issue(s + 2);

        const int st = s % 3;
        const uint32_t soA = (uint32_t)st * ASTG;
        const uint32_t soW = (uint32_t)st * WSTG;
#pragma unroll
        for (int kb = 0; kb < 4; kb++) {
            uint32_t a[MI][4];
#pragma unroll
            for (int mi = 0; mi < MI; mi++)
                LDSM_X4(a[mi][0], a[mi][1], a[mi][2], a[mi][3],
                        a_addr + soA + mi * 2304 + kb * 32);
            uint32_t b[4][2];
#pragma unroll
            for (int nb = 0; nb < 2; nb++)
                LDSM_X4_T(b[2 * nb][0], b[2 * nb][1], b[2 * nb + 1][0], b[2 * nb + 1][1],
                          w_addr + soW + nb * 32 + kb * 4352);
#pragma unroll
            for (int mi = 0; mi < MI; mi++)
#pragma unroll
                for (int ni = 0; ni < 4; ni++)
                    MMA_F16(acc[mi][ni], a[mi], b[ni][0], b[ni][1]);
        }
    }

    // Epilogue
#pragma unroll
    for (int mi = 0; mi < MI; mi++) {
#pragma unroll
        for (int r2 = 0; r2 < 2; r2++) {
            int row = bmRow + wm * (MR / 2) + mi * 16 + g + 8 * r2;
            int mslot = 0;
            if (PHASE == 0 && mode == 1) {
                int jj = row % JV;
                mslot = (jj < MEMR) ? (jj >> 10) : 4;
            }
#pragma unroll
            for (int ni = 0; ni < 4; ni++) {
                int col = bn + wn * 32 + ni * 8 + 2 * tg;
                float c0 = acc[mi][ni][r2 * 2];
                float c1 = acc[mi][ni][r2 * 2 + 1];
                if (PHASE == 1) {
                    Cout[(size_t)row * DIMV + col]     = c0 + bo[col];
                    Cout[(size_t)row * DIMV + col + 1] = c1 + bo[col + 1];
                } else if (mode == 0) {
                    *(__half2*)(g_Qh + (size_t)row * DIMV + col) =
                        __floats2half2_rn(c0, c1);
                } else if (mode == 1) {
                    float bias = rel_table[rel_idxs[mslot] * HEADS + (col >> 6)];
                    *(__half2*)(g_Kh + (size_t)row * DIMV + col) =
                        __floats2half2_rn(c0 + bias, c1 + bias);
                } else {
                    int jj = row % JV, bb = row / JV;
                    int hh = col >> 6, d = col & 63;
                    __half* p = g_VhT + ((size_t)(bb * HEADS + hh) * DHV + d) * JV + jj;
                    p[0]  = __float2half(c0);
                    p[JV] = __float2half(c1);
                }
            }
        }
    }
}

#define GEMM_SMEM0 (3 * (128 * 144 + WSTG))   // 107520
#define GEMM_SMEM1 (3 * (64 * 144 + WSTG))    // 79872

// ---------------------------------------------------------------------------
// Flash attention (R14 winner, unchanged): fp16 mma.sync, ldmatrix, Q frags
// hoisted, P in registers, K/V 4-stage cp.async, SIMD fp16x2 exp2 softmax,
// row-sum via ones-MMA. 8 warps, warp tile 16x64. Causal: j <= i + 4096.
// ---------------------------------------------------------------------------
#define QST 36
#define KST 36
#define VTS 36
#define KV_STG (64 * 144)
#define NSTG 4

__global__ __launch_bounds__(256, 2)
void attn_h()
{
    extern __shared__ uint32_t asmem[];
    uint32_t* Qs  = asmem;                     // [128][36]
    uint32_t* Ks  = Qs + 128 * QST;            // [4][64][36]
    uint32_t* VsT = Ks + NSTG * 64 * KST;      // [4][64][36]

    const int qt  = blockIdx.x;
    const int bh  = blockIdx.y;
    const int b   = bh >> 4;
    const int h   = bh & 15;
    const int tid = threadIdx.x;
    const int warp = tid >> 5;
    const int lane = tid & 31;
    const int g    = lane >> 2;
    const int tg   = lane & 3;
    const int q0   = qt * 128;
    const int rb   = warp * 16;
    const uint32_t ONE2 = 0x3C003C00u;         // packed fp16 {1, 1}

    // Load Q tile into smem
    {
        int qrow = tid >> 1, qc = (tid & 1) * 32;
        const __half* src = g_Qh + ((size_t)(b * NV + q0 + qrow)) * DIMV + h * DHV + qc;
#pragma unroll
        for (int p = 0; p < 4; p++)
            *(uint4*)&Qs[qrow * QST + (qc >> 1) + 4 * p] = ((const uint4*)src)[p];
    }

    float o[8][4];
    float m_i[2], l_i[2];
#pragma unroll
    for (int rh = 0; rh < 2; rh++) { m_i[rh] = -INFINITY; l_i[rh] = 0.f; }
#pragma unroll
    for (int ni = 0; ni < 8; ni++)
#pragma unroll
        for (int r = 0; r < 4; r++) o[ni][r] = 0.f;

    const int ktiles = 2 * qt + 66;

    const int kj  = tid >> 2;
    const int kch = (tid & 3) * 16;
    const __half* kbase = g_Kh + ((size_t)(b * JV + kj)) * DIMV + h * DHV + kch;
    const int vd = tid >> 2;
    const int vq = (tid & 3) * 8;
    const __half* vbase = g_VhT + (((size_t)(b * HEADS + h) * DHV + vd) * JV) + vq * 2;

    const uint32_t ksd = sptr(Ks)  + kj * 144 + (tid & 3) * 32;
    const uint32_t vsd = sptr(VsT) + vd * 144 + (tid & 3) * 32;

    const uint32_t q_addr =
        sptr(Qs) + (uint32_t)((rb + (lane & 15)) * 144 + (lane >> 4) * 16);
    const uint32_t kv_lane =
        (uint32_t)((((lane >> 4) * 8 + (lane & 7)) * 36 + 4 * ((lane >> 3) & 1)) * 4);
    const uint32_t ks_base = sptr(Ks) + kv_lane;
    const uint32_t vs_base = sptr(VsT) + kv_lane;

    auto issue_kv = [&](int tile) {
        const uint32_t so = (uint32_t)(tile % NSTG) * KV_STG;
        const __half* kp_ = kbase + (size_t)tile * 64 * DIMV;
        const __half* vp_ = vbase + (size_t)tile * 64;
        CP16(ksd + so, kp_); CP16(ksd + so + 16, kp_ + 8);
        CP16(vsd + so, vp_); CP16(vsd + so + 16, vp_ + 8);
        CP_COMMIT();
    };

    issue_kv(0); issue_kv(1); issue_kv(2);
    __syncthreads();   // Q smem visible

    uint32_t aq[4][4];
#pragma unroll
    for (int kb = 0; kb < 4; kb++)
        LDSM_X4(aq[kb][0], aq[kb][1], aq[kb][2], aq[kb][3], q_addr + kb * 32);

    for (int kt = 0; kt < ktiles; kt++) {
        if (kt + 2 < ktiles)      { CP_WAIT2(); }
        else if (kt + 1 < ktiles) { CP_WAIT1(); }
        else                      { CP_WAIT0(); }
        __syncthreads();

        if (kt + 3 < ktiles) issue_kv(kt + 3);

        const uint32_t so = (uint32_t)(kt % NSTG) * KV_STG;
        const uint32_t kst = ks_base + so;
        const uint32_t vst = vs_base + so;

        // S = Q K^T (log2 domain)
        float s[8][4];
#pragma unroll
        for (int ni = 0; ni < 8; ni++)
#pragma unroll
            for (int r = 0; r < 4; r++) s[ni][r] = 0.f;
#pragma unroll
        for (int kb = 0; kb < 4; kb++) {
#pragma unroll
            for (int nq = 0; nq < 4; nq++) {
                uint32_t b0, b1, b2, b3;
                LDSM_X4(b0, b1, b2, b3, kst + nq * (16 * 144) + kb * 32);
                MMA_F16(s[2 * nq],     aq[kb], b0, b1);
                MMA_F16(s[2 * nq + 1], aq[kb], b2, b3);
            }
        }

        // Causal mask on boundary tiles
        const int j0 = kt * 64;
        if (kt >= 2 * qt + 64) {
#pragma unroll
            for (int rh = 0; rh < 2; rh++) {
                int ii = q0 + rb + g + 8 * rh;
#pragma unroll
                for (int ni = 0; ni < 8; ni++)
#pragma unroll
                    for (int c2 = 0; c2 < 2; c2++) {
                        int jc = j0 + ni * 8 + 2 * tg + c2;
                        if (jc > ii + 4096) s[ni][rh * 2 + c2] = -1e30f;
                    }
            }
        }

        // Online softmax (exp2 domain): max-reduce + SIMD ex2; row sum via
        // tensor core below (P x ones).
        uint32_t pa[8][2];
        float fac[2];
#pragma unroll
        for (int rh = 0; rh < 2; rh++) {
            float mx = -INFINITY;
#pragma unroll
            for (int ni = 0; ni < 8; ni++)
                mx = fmaxf(mx, fmaxf(s[ni][2 * rh], s[ni][2 * rh + 1]));
            mx = fmaxf(mx, __shfl_xor_sync(0xffffffffu, mx, 1));
            mx = fmaxf(mx, __shfl_xor_sync(0xffffffffu, mx, 2));
            float mnew = fmaxf(m_i[rh], mx);
            fac[rh] = ex2f(m_i[rh] - mnew);
            m_i[rh] = mnew;
#pragma unroll
            for (int ni = 0; ni < 8; ni++)
                pa[ni][rh] = ex2h2(pack2(s[ni][2 * rh] - mnew,
                                         s[ni][2 * rh + 1] - mnew));
#pragma unroll
            for (int ni = 0; ni < 8; ni++) {
                o[ni][2 * rh]     *= fac[rh];
                o[ni][2 * rh + 1] *= fac[rh];
            }
        }

        // O += P V, and lsum = P x ones (row sums on the tensor pipe)
        float lsum[4] = { 0.f, 0.f, 0.f, 0.f };
#pragma unroll
        for (int kb = 0; kb < 4; kb++) {
            uint32_t a[4] = { pa[2 * kb][0], pa[2 * kb][1],
                              pa[2 * kb + 1][0], pa[2 * kb + 1][1] };
            MMA_F16(lsum, a, ONE2, ONE2);
#pragma unroll
            for (int nq = 0; nq < 4; nq++) {
                uint32_t b0, b1, b2, b3;
                LDSM_X4(b0, b1, b2, b3, vst + nq * (16 * 144) + kb * 32);
                MMA_F16(o[2 * nq],     a, b0, b1);
                MMA_F16(o[2 * nq + 1], a, b2, b3);
            }
        }
        l_i[0] = l_i[0] * fac[0] + lsum[0];
        l_i[1] = l_i[1] * fac[1] + lsum[2];
    }

    // Normalize, write O (fp16)
#pragma unroll
    for (int rh = 0; rh < 2; rh++) {
        float inv = 1.f / l_i[rh];
        int row = q0 + rb + g + 8 * rh;
        __half* dst = g_Oh + (size_t)(b * NV + row) * DIMV + h * DHV;
#pragma unroll
        for (int ni = 0; ni < 8; ni++) {
            *(__half2*)(dst + ni * 8 + 2 * tg) =
                __floats2half2_rn(o[ni][2 * rh] * inv, o[ni][2 * rh + 1] * inv);
        }
    }
}

static const size_t ATTN_SMEM =
    (size_t)(128 * QST + NSTG * 64 * KST + NSTG * 64 * VTS) * sizeof(uint32_t); // 92160

extern "C" void kernel_launch(void* const* d_in, const int* in_sizes, int n_in,
                              void* d_out, int out_size)
{
    const float* x    = (const float*)d_in[0];
    const float* mem  = (const float*)d_in[1];
    const int*   ridx = (const int*)d_in[3];
    const float* Wq   = (const float*)d_in[4];
    const float* Wk   = (const float*)d_in[5];
    const float* Wv   = (const float*)d_in[6];
    const float* Wo   = (const float*)d_in[7];
    const float* bo   = (const float*)d_in[8];
    const float* rtab = (const float*)d_in[9];
    float* out = (float*)d_out;

    cudaFuncSetAttribute(attn_h, cudaFuncAttributeMaxDynamicSharedMemorySize,
                         (int)ATTN_SMEM);
    cudaFuncSetAttribute(gemm_h<0>, cudaFuncAttributeMaxDynamicSharedMemorySize,
                         GEMM_SMEM0);
    cudaFuncSetAttribute(gemm_h<1>, cudaFuncAttributeMaxDynamicSharedMemorySize,
                         GEMM_SMEM1);

    conv_all<<<9216, 256>>>(x, mem, Wq, Wk, Wv, Wo,
                            out + (size_t)BV * NV * DIMV);
    gemm_h<0><<<dim3(8, 176), 256, GEMM_SMEM0>>>(ridx, rtab, bo, nullptr);
    attn_h<<<dim3(8, 32), 256, ATTN_SMEM>>>();
    gemm_h<1><<<dim3(8, 32), 256, GEMM_SMEM1>>>(ridx, rtab, bo, out);
}